// round 10
// baseline (speedup 1.0000x reference)
#include <cuda_runtime.h>
#include <math.h>
#include <float.h>

// Problem: points [8, 1M, 3] float32 uniform [0,1); RADIUS=0.05 -> keys in [0,19]
// Output buffer dtype: float32.
#define NB   8
#define HS   8000     // 20*20*20 possible voxels per batch
#define ABLK 37       // keys blocks per batch: 37*8=296 = 2/SM, one wave (best measured)
#define GBLK 74       // gather blocks per batch: 74*8=592 = 4/SM, one wave
#define REP  8        // global-RED replicas per batch
#define MAXP 8000000

struct BinTable { float t[22]; };   // t[k] = smallest float x with rn(x/0.05f) >= k

// Device scratch (no allocations allowed)
__device__ int          g_part[NB * ABLK * HS];  // per-block smem-partial histograms
__device__ int          g_red [NB * REP * HS];   // global-RED replicated histograms
                                                 // (zero at load; k_mid re-zeros after read)
__device__ unsigned int g_pk[NB * HS];           // packed (count | rank<<16)
__device__ ushort4      g_lin4[MAXP / 4];        // per-point linear voxel keys (16 MB)

// Kernel A: keys + lin + histogram. Even warps count via smem atomics,
// odd warps via replicated global RED -> two independent atomic back-ends.
// grid=(ABLK,NB), block=512, 4 points per thread-iteration.
__global__ void k_keys(const float* __restrict__ pts,
                       float* __restrict__ keys_out, int N, BinTable bt) {
    __shared__ int   sh[HS];
    __shared__ float sT[22];
    if (threadIdx.x < 22) sT[threadIdx.x] = bt.t[threadIdx.x];
    for (int i = threadIdx.x; i < HS; i += blockDim.x) sh[i] = 0;
    __syncthreads();

    const int b    = blockIdx.y;
    const int wid  = threadIdx.x >> 5;
    const bool use_smem = (wid & 1) == 0;
    int* __restrict__ red = g_red + (b * REP + ((wid >> 1) & (REP - 1))) * HS;

    const int G = N >> 2;
    const int per = (G + gridDim.x - 1) / gridDim.x;
    const int g0 = blockIdx.x * per;
    const int g1 = min(g0 + per, G);

    for (int g = g0 + (int)threadIdx.x; g < g1; g += blockDim.x) {
        long long p0 = (long long)b * N + (long long)g * 4;
        const float4* p4 = (const float4*)(pts + p0 * 3);
        float4 A = __ldcs(p4 + 0), B4 = __ldcs(p4 + 1), C = __ldcs(p4 + 2);
        float v[12] = {A.x, A.y, A.z, A.w, B4.x, B4.y, B4.z, B4.w, C.x, C.y, C.z, C.w};

        int k[12];
#pragma unroll
        for (int i = 0; i < 12; i++) {
            // Fast approx bin + exact boundary fixup: equals floor(rn(v/0.05f)).
            int kk = (int)(v[i] * 20.0f);
            kk = min(kk, 20);
            if (v[i] >= sT[kk + 1])    kk++;
            else if (v[i] < sT[kk])    kk--;
            k[i] = kk;
        }

        float4* ko = (float4*)(keys_out + p0 * 3);
        __stcs(ko + 0, make_float4((float)k[0], (float)k[1], (float)k[2],  (float)k[3]));
        __stcs(ko + 1, make_float4((float)k[4], (float)k[5], (float)k[6],  (float)k[7]));
        __stcs(ko + 2, make_float4((float)k[8], (float)k[9], (float)k[10], (float)k[11]));

        unsigned short lin[4];
#pragma unroll
        for (int i = 0; i < 4; i++) {
            // Fixed lexicographic linearization; order-equivalent to the
            // reference's data-dependent row-major strides.
            int l = k[3 * i] * 400 + k[3 * i + 1] * 20 + k[3 * i + 2];
            l = min(max(l, 0), HS - 1);
            lin[i] = (unsigned short)l;
            if (use_smem) atomicAdd(&sh[l], 1);
            else          atomicAdd(&red[l], 1);   // return unused -> REDG
        }
        g_lin4[p0 >> 2] = make_ushort4(lin[0], lin[1], lin[2], lin[3]);
    }
    __syncthreads();

    int* dst = g_part + (b * ABLK + blockIdx.x) * HS;
    for (int i = threadIdx.x; i < HS; i += blockDim.x) dst[i] = sh[i];
}

// Kernel M: fused reduce (smem partials + RED replicas) + occupancy scan + pack.
// One block per batch, 1024 threads. Re-zeros g_red for the next graph replay.
__global__ void k_mid(float* __restrict__ binmap_out) {
    __shared__ int cnt[HS];             // 32 KB
    __shared__ unsigned short rnk[HS];  // 16 KB
    __shared__ int wsum[32];

    const int b   = blockIdx.x;
    const int tid = threadIdx.x;

    for (int i = tid; i < HS; i += 1024) {
        int s = 0;
#pragma unroll
        for (int j = 0; j < ABLK; j++) s += g_part[(b * ABLK + j) * HS + i];
#pragma unroll
        for (int j = 0; j < REP; j++) {
            int* p = &g_red[(b * REP + j) * HS + i];
            s += *p;
            *p = 0;                      // restore invariant for next launch
        }
        cnt[i] = s;
    }
    __syncthreads();

    const int PER = 8;                  // 1024 * 8 = 8192 >= HS
    int base0 = tid * PER;
    int occ = 0;
#pragma unroll
    for (int i = 0; i < PER; i++) {
        int idx = base0 + i;
        if (idx < HS) occ += (cnt[idx] > 0) ? 1 : 0;
    }

    int lane = tid & 31, wid = tid >> 5;
    int inc = occ;
#pragma unroll
    for (int off = 1; off < 32; off <<= 1) {
        int v = __shfl_up_sync(0xFFFFFFFF, inc, off);
        if (lane >= off) inc += v;
    }
    if (lane == 31) wsum[wid] = inc;
    __syncthreads();
    if (wid == 0) {
        int w = wsum[lane];
#pragma unroll
        for (int off = 1; off < 32; off <<= 1) {
            int v = __shfl_up_sync(0xFFFFFFFF, w, off);
            if (lane >= off) w += v;
        }
        wsum[lane] = w;
    }
    __syncthreads();
    int warpBase = (wid > 0) ? wsum[wid - 1] : 0;
    int tBase = warpBase + inc - occ;

    int run = tBase;
#pragma unroll
    for (int i = 0; i < PER; i++) {
        int idx = base0 + i;
        if (idx < HS) {
            rnk[idx] = (unsigned short)run;
            run += (cnt[idx] > 0) ? 1 : 0;
        }
    }
    __syncthreads();

    for (int i = tid; i < HS; i += 1024) {
        unsigned int c = (unsigned int)min(cnt[i], 0xFFFF);
        g_pk[b * HS + i] = c | ((unsigned int)rnk[i] << 16);
    }

    if (b == 0 && tid < 27) {
        binmap_out[tid * 3 + 0] = (float)((tid / 9) - 1);
        binmap_out[tid * 3 + 1] = (float)(((tid / 3) % 3) - 1);
        binmap_out[tid * 3 + 2] = (float)((tid % 3) - 1);
    }
}

// Kernel G: gather via smem-resident packed table. grid=(GBLK,NB), block=512.
__global__ void k_gather(float* __restrict__ vox_out,
                         float* __restrict__ cnt_out, int N) {
    __shared__ unsigned int st[HS];   // 32 KB
    const int b = blockIdx.y;
    for (int i = threadIdx.x; i < HS; i += blockDim.x) st[i] = g_pk[b * HS + i];
    __syncthreads();

    const int G = N >> 2;
    const int per = (G + gridDim.x - 1) / gridDim.x;
    const int g0 = blockIdx.x * per;
    const int g1 = min(g0 + per, G);

    for (int g = g0 + (int)threadIdx.x; g < g1; g += blockDim.x) {
        long long p0 = (long long)b * N + (long long)g * 4;
        ushort4 l4 = g_lin4[p0 >> 2];

        unsigned int a = st[l4.x], c = st[l4.y], d = st[l4.z], e = st[l4.w];

        __stcs((float4*)(cnt_out + p0), make_float4(
            (float)(a & 0xFFFF), (float)(c & 0xFFFF),
            (float)(d & 0xFFFF), (float)(e & 0xFFFF)));
        __stcs((float4*)(vox_out + p0), make_float4(
            (float)(a >> 16), (float)(c >> 16),
            (float)(d >> 16), (float)(e >> 16)));
    }
}

extern "C" void kernel_launch(void* const* d_in, const int* in_sizes, int n_in,
                              void* d_out, int out_size) {
    const float* pts = (const float*)d_in[0];
    int total = in_sizes[0] / 3;     // 8,000,000
    int N     = total / NB;          // 1,000,000 (multiple of 4)

    float* out      = (float*)d_out;
    float* keys_out = out;                         // [B, N, 3]
    float* vox_out  = out + (long long)total * 3;  // [B, N]
    float* cnt_out  = vox_out + total;             // [B, N]
    float* bm_out   = cnt_out + total;             // [27, 3]

    // Exact bin boundaries via host IEEE fp32 division (same rn semantics as
    // device __fdiv_rn). Deterministic; recomputed every call.
    BinTable bt;
    bt.t[0] = 0.0f;
    bt.t[21] = FLT_MAX;
    for (int k = 1; k <= 20; k++) {
        volatile float c = (float)k * 0.05f;
        while ((float)(c / 0.05f) < (float)k) c = nextafterf(c, FLT_MAX);
        for (;;) {
            float p = nextafterf(c, -FLT_MAX);
            if ((float)(p / 0.05f) >= (float)k) c = p; else break;
        }
        bt.t[k] = c;
    }

    k_keys<<<dim3(ABLK, NB), 512>>>(pts, keys_out, N, bt);
    k_mid<<<NB, 1024>>>(bm_out);
    k_gather<<<dim3(GBLK, NB), 512>>>(vox_out, cnt_out, N);
}

// round 11
// speedup vs baseline: 1.2794x; 1.2794x over previous
#include <cuda_runtime.h>
#include <math.h>

// Problem: points [8, 1M, 3] float32 uniform [0,1); RADIUS=0.05 -> keys in [0,19]
// Output buffer dtype: float32.
#define NB   8
#define HS   8000     // 20*20*20 possible voxels per batch
#define ABLK 37       // keys blocks per batch: 37*8=296 = 2/SM, one wave (measured best)
#define GBLK 37       // gather blocks per batch
#define MAXP 8000000

// Device scratch (no allocations allowed)
__device__ int          g_part[NB * ABLK * HS];  // per-block partial histograms (9.5 MB)
__device__ unsigned int g_pk[NB * HS];           // packed (count | rank<<16)
__device__ uint4        g_lin4[MAXP / 8];        // per-point linear voxel keys as ushorts,
                                                 // 16B-aligned for uint4 gather loads

// Kernel A: keys + lin + smem-privatized histogram.
// grid=(ABLK,NB), block=512, 4 points per thread-iteration.
// Binning uses IEEE correctly-rounded division (matches jnp's x/0.05 in fp32);
// MUFU/FMA pipes are idle here while the smem crossbar (atomics) is the
// bottleneck, so the division is effectively free.
__global__ void k_keys(const float* __restrict__ pts,
                       float* __restrict__ keys_out, int N) {
    __shared__ int sh[HS];
    for (int i = threadIdx.x; i < HS; i += blockDim.x) sh[i] = 0;
    __syncthreads();

    const int b = blockIdx.y;
    const int G = N >> 2;
    const int per = (G + gridDim.x - 1) / gridDim.x;
    const int g0 = blockIdx.x * per;
    const int g1 = min(g0 + per, G);

    for (int g = g0 + (int)threadIdx.x; g < g1; g += blockDim.x) {
        long long p0 = (long long)b * N + (long long)g * 4;
        const float4* p4 = (const float4*)(pts + p0 * 3);
        float4 A = p4[0], B4 = p4[1], C = p4[2];
        float v[12] = {A.x, A.y, A.z, A.w, B4.x, B4.y, B4.z, B4.w, C.x, C.y, C.z, C.w};

        int k[12];
#pragma unroll
        for (int i = 0; i < 12; i++)
            k[i] = (int)floorf(__fdiv_rn(v[i], 0.05f));

        float4* ko = (float4*)(keys_out + p0 * 3);
        ko[0] = make_float4((float)k[0], (float)k[1], (float)k[2],  (float)k[3]);
        ko[1] = make_float4((float)k[4], (float)k[5], (float)k[6],  (float)k[7]);
        ko[2] = make_float4((float)k[8], (float)k[9], (float)k[10], (float)k[11]);

        unsigned short lin[4];
#pragma unroll
        for (int i = 0; i < 4; i++) {
            // Fixed lexicographic linearization; order-equivalent to the
            // reference's data-dependent row-major strides.
            int l = k[3 * i] * 400 + k[3 * i + 1] * 20 + k[3 * i + 2];
            l = min(max(l, 0), HS - 1);
            lin[i] = (unsigned short)l;
            atomicAdd(&sh[l], 1);
        }
        ((ushort4*)g_lin4)[p0 >> 2] = make_ushort4(lin[0], lin[1], lin[2], lin[3]);
    }
    __syncthreads();

    int* dst = g_part + (b * ABLK + blockIdx.x) * HS;
    for (int i = threadIdx.x; i < HS; i += blockDim.x) dst[i] = sh[i];
}

// Kernel M: fused reduce + occupancy scan + pack. One block per batch, 1024 threads.
__global__ void k_mid(float* __restrict__ binmap_out) {
    __shared__ int cnt[HS];             // 32 KB
    __shared__ unsigned short rnk[HS];  // 16 KB
    __shared__ int wsum[32];

    const int b   = blockIdx.x;
    const int tid = threadIdx.x;

    for (int i = tid; i < HS; i += 1024) {
        int s = 0;
#pragma unroll
        for (int j = 0; j < ABLK; j++) s += g_part[(b * ABLK + j) * HS + i];
        cnt[i] = s;
    }
    __syncthreads();

    const int PER = 8;                  // 1024 * 8 = 8192 >= HS
    int base0 = tid * PER;
    int occ = 0;
#pragma unroll
    for (int i = 0; i < PER; i++) {
        int idx = base0 + i;
        if (idx < HS) occ += (cnt[idx] > 0) ? 1 : 0;
    }

    int lane = tid & 31, wid = tid >> 5;
    int inc = occ;
#pragma unroll
    for (int off = 1; off < 32; off <<= 1) {
        int v = __shfl_up_sync(0xFFFFFFFF, inc, off);
        if (lane >= off) inc += v;
    }
    if (lane == 31) wsum[wid] = inc;
    __syncthreads();
    if (wid == 0) {
        int w = wsum[lane];
#pragma unroll
        for (int off = 1; off < 32; off <<= 1) {
            int v = __shfl_up_sync(0xFFFFFFFF, w, off);
            if (lane >= off) w += v;
        }
        wsum[lane] = w;
    }
    __syncthreads();
    int warpBase = (wid > 0) ? wsum[wid - 1] : 0;
    int tBase = warpBase + inc - occ;

    int run = tBase;
#pragma unroll
    for (int i = 0; i < PER; i++) {
        int idx = base0 + i;
        if (idx < HS) {
            rnk[idx] = (unsigned short)run;
            run += (cnt[idx] > 0) ? 1 : 0;
        }
    }
    __syncthreads();

    for (int i = tid; i < HS; i += 1024) {
        unsigned int c = (unsigned int)min(cnt[i], 0xFFFF);
        g_pk[b * HS + i] = c | ((unsigned int)rnk[i] << 16);
    }

    if (b == 0 && tid < 27) {
        binmap_out[tid * 3 + 0] = (float)((tid / 9) - 1);
        binmap_out[tid * 3 + 1] = (float)(((tid / 3) % 3) - 1);
        binmap_out[tid * 3 + 2] = (float)((tid % 3) - 1);
    }
}

// Kernel G: gather via smem-resident packed table. grid=(GBLK,NB), block=512.
// 8 points per thread-iteration: one uint4 (8 ushorts) lin load, 8 LDS, 4 STG.128.
__global__ void k_gather(float* __restrict__ vox_out,
                         float* __restrict__ cnt_out, int N) {
    __shared__ unsigned int st[HS];   // 32 KB
    const int b = blockIdx.y;
    for (int i = threadIdx.x; i < HS; i += blockDim.x) st[i] = g_pk[b * HS + i];
    __syncthreads();

    const int G = N >> 3;             // 8-point groups
    const int per = (G + gridDim.x - 1) / gridDim.x;
    const int g0 = blockIdx.x * per;
    const int g1 = min(g0 + per, G);

    for (int g = g0 + (int)threadIdx.x; g < g1; g += blockDim.x) {
        long long p0 = (long long)b * N + (long long)g * 8;
        uint4 lw = g_lin4[p0 >> 3];
        unsigned int l[8] = {
            lw.x & 0xFFFF, lw.x >> 16, lw.y & 0xFFFF, lw.y >> 16,
            lw.z & 0xFFFF, lw.z >> 16, lw.w & 0xFFFF, lw.w >> 16
        };

        unsigned int pk[8];
#pragma unroll
        for (int i = 0; i < 8; i++) pk[i] = st[l[i]];

        float4* co = (float4*)(cnt_out + p0);
        float4* vo = (float4*)(vox_out + p0);
        co[0] = make_float4((float)(pk[0] & 0xFFFF), (float)(pk[1] & 0xFFFF),
                            (float)(pk[2] & 0xFFFF), (float)(pk[3] & 0xFFFF));
        co[1] = make_float4((float)(pk[4] & 0xFFFF), (float)(pk[5] & 0xFFFF),
                            (float)(pk[6] & 0xFFFF), (float)(pk[7] & 0xFFFF));
        vo[0] = make_float4((float)(pk[0] >> 16), (float)(pk[1] >> 16),
                            (float)(pk[2] >> 16), (float)(pk[3] >> 16));
        vo[1] = make_float4((float)(pk[4] >> 16), (float)(pk[5] >> 16),
                            (float)(pk[6] >> 16), (float)(pk[7] >> 16));
    }
}

extern "C" void kernel_launch(void* const* d_in, const int* in_sizes, int n_in,
                              void* d_out, int out_size) {
    const float* pts = (const float*)d_in[0];
    int total = in_sizes[0] / 3;     // 8,000,000
    int N     = total / NB;          // 1,000,000 (multiple of 8)

    float* out      = (float*)d_out;
    float* keys_out = out;                         // [B, N, 3]
    float* vox_out  = out + (long long)total * 3;  // [B, N]
    float* cnt_out  = vox_out + total;             // [B, N]
    float* bm_out   = cnt_out + total;             // [27, 3]

    k_keys<<<dim3(ABLK, NB), 512>>>(pts, keys_out, N);
    k_mid<<<NB, 1024>>>(bm_out);
    k_gather<<<dim3(GBLK, NB), 512>>>(vox_out, cnt_out, N);
}

// round 12
// speedup vs baseline: 1.3253x; 1.0359x over previous
#include <cuda_runtime.h>
#include <math.h>

// Problem: points [8, 1M, 3] float32 uniform [0,1); RADIUS=0.05 -> keys in [0,19]
// Output buffer dtype: float32.
#define NB   8
#define HS   8000     // 20*20*20 possible voxels per batch
#define ABLK 37       // keys blocks per batch: 37*8=296 = 2/SM, one wave (measured best)
#define MAXP 8000000

// Device scratch (no allocations allowed)
__device__ int          g_part[NB * ABLK * HS];  // per-block partial histograms (9.5 MB)
__device__ int          g_hist[NB * HS];         // reduced per-voxel counts
__device__ unsigned int g_pk[NB * HS];           // packed (count | rank<<16), 256 KB total
__device__ uint4        g_lin4[MAXP / 8];        // per-point lin keys (ushorts), 16B groups

// Kernel A: keys + lin + smem-privatized histogram.
// grid=(ABLK,NB), block=512, 4 points per thread-iteration.
// IEEE correctly-rounded division matches jnp's x/0.05 in fp32; MUFU/FMA are
// idle while the smem crossbar (atomics) binds, so it's effectively free.
__global__ void k_keys(const float* __restrict__ pts,
                       float* __restrict__ keys_out, int N) {
    __shared__ int sh[HS];
    for (int i = threadIdx.x; i < HS; i += blockDim.x) sh[i] = 0;
    __syncthreads();

    const int b = blockIdx.y;
    const int G = N >> 2;
    const int per = (G + gridDim.x - 1) / gridDim.x;
    const int g0 = blockIdx.x * per;
    const int g1 = min(g0 + per, G);

    for (int g = g0 + (int)threadIdx.x; g < g1; g += blockDim.x) {
        long long p0 = (long long)b * N + (long long)g * 4;
        const float4* p4 = (const float4*)(pts + p0 * 3);
        float4 A = p4[0], B4 = p4[1], C = p4[2];
        float v[12] = {A.x, A.y, A.z, A.w, B4.x, B4.y, B4.z, B4.w, C.x, C.y, C.z, C.w};

        int k[12];
#pragma unroll
        for (int i = 0; i < 12; i++)
            k[i] = (int)floorf(__fdiv_rn(v[i], 0.05f));

        float4* ko = (float4*)(keys_out + p0 * 3);
        ko[0] = make_float4((float)k[0], (float)k[1], (float)k[2],  (float)k[3]);
        ko[1] = make_float4((float)k[4], (float)k[5], (float)k[6],  (float)k[7]);
        ko[2] = make_float4((float)k[8], (float)k[9], (float)k[10], (float)k[11]);

        unsigned short lin[4];
#pragma unroll
        for (int i = 0; i < 4; i++) {
            // Fixed lexicographic linearization; order-equivalent to the
            // reference's data-dependent row-major strides.
            int l = k[3 * i] * 400 + k[3 * i + 1] * 20 + k[3 * i + 2];
            l = min(max(l, 0), HS - 1);
            lin[i] = (unsigned short)l;
            atomicAdd(&sh[l], 1);
        }
        ((ushort4*)g_lin4)[p0 >> 2] = make_ushort4(lin[0], lin[1], lin[2], lin[3]);
    }
    __syncthreads();

    int* dst = g_part + (b * ABLK + blockIdx.x) * HS;
    for (int i = threadIdx.x; i < HS; i += blockDim.x) dst[i] = sh[i];
}

// Kernel R: full-chip coalesced reduce of partials -> g_hist. Also bin_map.
__global__ void k_reduce(float* __restrict__ binmap_out) {
    int i = blockIdx.x * blockDim.x + threadIdx.x;   // b*HS + bin
    if (i < 27) {
        binmap_out[i * 3 + 0] = (float)((i / 9) - 1);
        binmap_out[i * 3 + 1] = (float)(((i / 3) % 3) - 1);
        binmap_out[i * 3 + 2] = (float)((i % 3) - 1);
    }
    if (i >= NB * HS) return;
    int b = i / HS;
    int bin = i - b * HS;
    int s = 0;
#pragma unroll
    for (int j = 0; j < ABLK; j++) s += g_part[(b * ABLK + j) * HS + bin];
    g_hist[i] = s;
}

// Kernel M: per-batch occupancy scan + pack (thin; reduce already done).
// One block per batch, 1024 threads.
__global__ void k_mid() {
    __shared__ int cnt[HS];             // 32 KB
    __shared__ unsigned short rnk[HS];  // 16 KB
    __shared__ int wsum[32];

    const int b   = blockIdx.x;
    const int tid = threadIdx.x;

    for (int i = tid; i < HS; i += 1024) cnt[i] = g_hist[b * HS + i];
    __syncthreads();

    const int PER = 8;                  // 1024 * 8 = 8192 >= HS
    int base0 = tid * PER;
    int occ = 0;
#pragma unroll
    for (int i = 0; i < PER; i++) {
        int idx = base0 + i;
        if (idx < HS) occ += (cnt[idx] > 0) ? 1 : 0;
    }

    int lane = tid & 31, wid = tid >> 5;
    int inc = occ;
#pragma unroll
    for (int off = 1; off < 32; off <<= 1) {
        int v = __shfl_up_sync(0xFFFFFFFF, inc, off);
        if (lane >= off) inc += v;
    }
    if (lane == 31) wsum[wid] = inc;
    __syncthreads();
    if (wid == 0) {
        int w = wsum[lane];
#pragma unroll
        for (int off = 1; off < 32; off <<= 1) {
            int v = __shfl_up_sync(0xFFFFFFFF, w, off);
            if (lane >= off) w += v;
        }
        wsum[lane] = w;
    }
    __syncthreads();
    int warpBase = (wid > 0) ? wsum[wid - 1] : 0;
    int tBase = warpBase + inc - occ;

    int run = tBase;
#pragma unroll
    for (int i = 0; i < PER; i++) {
        int idx = base0 + i;
        if (idx < HS) {
            rnk[idx] = (unsigned short)run;
            run += (cnt[idx] > 0) ? 1 : 0;
        }
    }
    __syncthreads();

    for (int i = tid; i < HS; i += 1024) {
        unsigned int c = (unsigned int)min(cnt[i], 0xFFFF);
        g_pk[b * HS + i] = c | ((unsigned int)rnk[i] << 16);
    }
}

// Kernel G: gather via L1/L2-resident packed table (no smem staging).
// grid=(ceil((N/8)/256), NB), block=256; 8 points per thread:
// one uint4 lin load, 8 scattered LDG.32 (table 32 KB/batch), 4 STG.128.
__global__ void k_gather(float* __restrict__ vox_out,
                         float* __restrict__ cnt_out, int N) {
    int b = blockIdx.y;
    int g = blockIdx.x * blockDim.x + threadIdx.x;
    if (g >= (N >> 3)) return;
    long long p0 = (long long)b * N + (long long)g * 8;

    uint4 lw = g_lin4[p0 >> 3];
    const unsigned int* __restrict__ t = g_pk + b * HS;

    unsigned int l[8] = {
        lw.x & 0xFFFF, lw.x >> 16, lw.y & 0xFFFF, lw.y >> 16,
        lw.z & 0xFFFF, lw.z >> 16, lw.w & 0xFFFF, lw.w >> 16
    };
    unsigned int pk[8];
#pragma unroll
    for (int i = 0; i < 8; i++) pk[i] = t[l[i]];

    float4* co = (float4*)(cnt_out + p0);
    float4* vo = (float4*)(vox_out + p0);
    co[0] = make_float4((float)(pk[0] & 0xFFFF), (float)(pk[1] & 0xFFFF),
                        (float)(pk[2] & 0xFFFF), (float)(pk[3] & 0xFFFF));
    co[1] = make_float4((float)(pk[4] & 0xFFFF), (float)(pk[5] & 0xFFFF),
                        (float)(pk[6] & 0xFFFF), (float)(pk[7] & 0xFFFF));
    vo[0] = make_float4((float)(pk[0] >> 16), (float)(pk[1] >> 16),
                        (float)(pk[2] >> 16), (float)(pk[3] >> 16));
    vo[1] = make_float4((float)(pk[4] >> 16), (float)(pk[5] >> 16),
                        (float)(pk[6] >> 16), (float)(pk[7] >> 16));
}

extern "C" void kernel_launch(void* const* d_in, const int* in_sizes, int n_in,
                              void* d_out, int out_size) {
    const float* pts = (const float*)d_in[0];
    int total = in_sizes[0] / 3;     // 8,000,000
    int N     = total / NB;          // 1,000,000 (multiple of 8)

    float* out      = (float*)d_out;
    float* keys_out = out;                         // [B, N, 3]
    float* vox_out  = out + (long long)total * 3;  // [B, N]
    float* cnt_out  = vox_out + total;             // [B, N]
    float* bm_out   = cnt_out + total;             // [27, 3]

    k_keys<<<dim3(ABLK, NB), 512>>>(pts, keys_out, N);
    k_reduce<<<(NB * HS + 255) / 256, 256>>>(bm_out);
    k_mid<<<NB, 1024>>>();
    k_gather<<<dim3(((N >> 3) + 255) / 256, NB), 256>>>(vox_out, cnt_out, N);
}

// round 13
// speedup vs baseline: 1.3264x; 1.0008x over previous
#include <cuda_runtime.h>
#include <math.h>

// Problem: points [8, 1M, 3] float32 uniform [0,1); RADIUS=0.05 -> keys in [0,19]
// Output buffer dtype: float32.
#define NB   8
#define HS   8000     // 20*20*20 possible voxels per batch
#define ABLK 37       // keys blocks per batch: 37*8=296 = 2/SM, one wave (measured best)
#define GBLK 37       // gather blocks per batch: 296 blocks x 1024 thr = 2/SM, one wave
#define MAXP 8000000

// Device scratch (no allocations allowed)
__device__ int          g_part[NB * ABLK * HS];  // per-block partial histograms (9.5 MB)
__device__ int          g_hist[NB * HS];         // reduced per-voxel counts
__device__ unsigned int g_pk[NB * HS];           // packed (count | rank<<16), 256 KB total
__device__ uint4        g_lin4[MAXP / 8];        // per-point lin keys (ushorts), 16B groups

// Kernel A: keys + lin + smem-privatized histogram.
// grid=(ABLK,NB), block=512, 4 points per thread-iteration.
// IEEE correctly-rounded division matches jnp's x/0.05 in fp32; MUFU/FMA are
// idle while the smem crossbar (atomics) binds, so it's effectively free.
__global__ void k_keys(const float* __restrict__ pts,
                       float* __restrict__ keys_out, int N) {
    __shared__ int sh[HS];
    for (int i = threadIdx.x; i < HS; i += blockDim.x) sh[i] = 0;
    __syncthreads();

    const int b = blockIdx.y;
    const int G = N >> 2;
    const int per = (G + gridDim.x - 1) / gridDim.x;
    const int g0 = blockIdx.x * per;
    const int g1 = min(g0 + per, G);

    for (int g = g0 + (int)threadIdx.x; g < g1; g += blockDim.x) {
        long long p0 = (long long)b * N + (long long)g * 4;
        const float4* p4 = (const float4*)(pts + p0 * 3);
        float4 A = p4[0], B4 = p4[1], C = p4[2];
        float v[12] = {A.x, A.y, A.z, A.w, B4.x, B4.y, B4.z, B4.w, C.x, C.y, C.z, C.w};

        int k[12];
#pragma unroll
        for (int i = 0; i < 12; i++)
            k[i] = (int)floorf(__fdiv_rn(v[i], 0.05f));

        float4* ko = (float4*)(keys_out + p0 * 3);
        ko[0] = make_float4((float)k[0], (float)k[1], (float)k[2],  (float)k[3]);
        ko[1] = make_float4((float)k[4], (float)k[5], (float)k[6],  (float)k[7]);
        ko[2] = make_float4((float)k[8], (float)k[9], (float)k[10], (float)k[11]);

        unsigned short lin[4];
#pragma unroll
        for (int i = 0; i < 4; i++) {
            // Fixed lexicographic linearization; order-equivalent to the
            // reference's data-dependent row-major strides.
            int l = k[3 * i] * 400 + k[3 * i + 1] * 20 + k[3 * i + 2];
            l = min(max(l, 0), HS - 1);
            lin[i] = (unsigned short)l;
            atomicAdd(&sh[l], 1);
        }
        ((ushort4*)g_lin4)[p0 >> 2] = make_ushort4(lin[0], lin[1], lin[2], lin[3]);
    }
    __syncthreads();

    int* dst = g_part + (b * ABLK + blockIdx.x) * HS;
    for (int i = threadIdx.x; i < HS; i += blockDim.x) dst[i] = sh[i];
}

// Kernel R: full-chip coalesced reduce of partials -> g_hist. Also bin_map.
__global__ void k_reduce(float* __restrict__ binmap_out) {
    int i = blockIdx.x * blockDim.x + threadIdx.x;   // b*HS + bin
    if (i < 27) {
        binmap_out[i * 3 + 0] = (float)((i / 9) - 1);
        binmap_out[i * 3 + 1] = (float)(((i / 3) % 3) - 1);
        binmap_out[i * 3 + 2] = (float)((i % 3) - 1);
    }
    if (i >= NB * HS) return;
    int b = i / HS;
    int bin = i - b * HS;
    int s = 0;
#pragma unroll
    for (int j = 0; j < ABLK; j++) s += g_part[(b * ABLK + j) * HS + bin];
    g_hist[i] = s;
}

// Kernel M: per-batch occupancy scan + pack. One block per batch, 1024 threads.
__global__ void k_mid() {
    __shared__ int cnt[HS];             // 32 KB
    __shared__ unsigned short rnk[HS];  // 16 KB
    __shared__ int wsum[32];

    const int b   = blockIdx.x;
    const int tid = threadIdx.x;

    for (int i = tid; i < HS; i += 1024) cnt[i] = g_hist[b * HS + i];
    __syncthreads();

    const int PER = 8;                  // 1024 * 8 = 8192 >= HS
    int base0 = tid * PER;
    int occ = 0;
#pragma unroll
    for (int i = 0; i < PER; i++) {
        int idx = base0 + i;
        if (idx < HS) occ += (cnt[idx] > 0) ? 1 : 0;
    }

    int lane = tid & 31, wid = tid >> 5;
    int inc = occ;
#pragma unroll
    for (int off = 1; off < 32; off <<= 1) {
        int v = __shfl_up_sync(0xFFFFFFFF, inc, off);
        if (lane >= off) inc += v;
    }
    if (lane == 31) wsum[wid] = inc;
    __syncthreads();
    if (wid == 0) {
        int w = wsum[lane];
#pragma unroll
        for (int off = 1; off < 32; off <<= 1) {
            int v = __shfl_up_sync(0xFFFFFFFF, w, off);
            if (lane >= off) w += v;
        }
        wsum[lane] = w;
    }
    __syncthreads();
    int warpBase = (wid > 0) ? wsum[wid - 1] : 0;
    int tBase = warpBase + inc - occ;

    int run = tBase;
#pragma unroll
    for (int i = 0; i < PER; i++) {
        int idx = base0 + i;
        if (idx < HS) {
            rnk[idx] = (unsigned short)run;
            run += (cnt[idx] > 0) ? 1 : 0;
        }
    }
    __syncthreads();

    for (int i = tid; i < HS; i += 1024) {
        unsigned int c = (unsigned int)min(cnt[i], 0xFFFF);
        g_pk[b * HS + i] = c | ((unsigned int)rnk[i] << 16);
    }
}

// Kernel G: gather via smem-staged packed table (LDS conflicts ~4 cyc/warp vs
// ~31 L1 wavefronts/warp for scattered LDG — the R12 profile's binding cost).
// grid=(GBLK,NB)=296 blocks x 1024 thr = 2 blocks/SM, one wave.
// 8 points per thread-iteration: one uint4 lin load, 8 LDS, 4 STG.128.
__global__ void k_gather(float* __restrict__ vox_out,
                         float* __restrict__ cnt_out, int N) {
    __shared__ unsigned int st[HS];   // 32 KB
    const int b = blockIdx.y;
    for (int i = threadIdx.x; i < HS; i += blockDim.x) st[i] = g_pk[b * HS + i];
    __syncthreads();

    const int G = N >> 3;             // 8-point groups per batch
    const int per = (G + gridDim.x - 1) / gridDim.x;
    const int g0 = blockIdx.x * per;
    const int g1 = min(g0 + per, G);

    for (int g = g0 + (int)threadIdx.x; g < g1; g += blockDim.x) {
        long long p0 = (long long)b * N + (long long)g * 8;
        uint4 lw = __ldcs(&g_lin4[p0 >> 3]);

        unsigned int l[8] = {
            lw.x & 0xFFFF, lw.x >> 16, lw.y & 0xFFFF, lw.y >> 16,
            lw.z & 0xFFFF, lw.z >> 16, lw.w & 0xFFFF, lw.w >> 16
        };
        unsigned int pk[8];
#pragma unroll
        for (int i = 0; i < 8; i++) pk[i] = st[l[i]];

        float4* co = (float4*)(cnt_out + p0);
        float4* vo = (float4*)(vox_out + p0);
        __stcs(co + 0, make_float4((float)(pk[0] & 0xFFFF), (float)(pk[1] & 0xFFFF),
                                   (float)(pk[2] & 0xFFFF), (float)(pk[3] & 0xFFFF)));
        __stcs(co + 1, make_float4((float)(pk[4] & 0xFFFF), (float)(pk[5] & 0xFFFF),
                                   (float)(pk[6] & 0xFFFF), (float)(pk[7] & 0xFFFF)));
        __stcs(vo + 0, make_float4((float)(pk[0] >> 16), (float)(pk[1] >> 16),
                                   (float)(pk[2] >> 16), (float)(pk[3] >> 16)));
        __stcs(vo + 1, make_float4((float)(pk[4] >> 16), (float)(pk[5] >> 16),
                                   (float)(pk[6] >> 16), (float)(pk[7] >> 16)));
    }
}

extern "C" void kernel_launch(void* const* d_in, const int* in_sizes, int n_in,
                              void* d_out, int out_size) {
    const float* pts = (const float*)d_in[0];
    int total = in_sizes[0] / 3;     // 8,000,000
    int N     = total / NB;          // 1,000,000 (multiple of 8)

    float* out      = (float*)d_out;
    float* keys_out = out;                         // [B, N, 3]
    float* vox_out  = out + (long long)total * 3;  // [B, N]
    float* cnt_out  = vox_out + total;             // [B, N]
    float* bm_out   = cnt_out + total;             // [27, 3]

    k_keys<<<dim3(ABLK, NB), 512>>>(pts, keys_out, N);
    k_reduce<<<(NB * HS + 255) / 256, 256>>>(bm_out);
    k_mid<<<NB, 1024>>>();
    k_gather<<<dim3(GBLK, NB), 1024>>>(vox_out, cnt_out, N);
}